// round 4
// baseline (speedup 1.0000x reference)
#include <cuda_runtime.h>

#define FDIM 128
#define NN   50000
#define EMAX 800000
#define NBMAX 64

// ---------------- scratch (device globals) ----------------------------------
static __device__ float g_agg[(size_t)NN * FDIM];
static __device__ float g_h  [(size_t)NN * FDIM];
static __device__ float g_h2 [(size_t)NN * FDIM];
static __device__ float g_bn [256];    // [0:128) sum, [128:256) sumsq
static __device__ float g_bnab[256];   // [0:128) scale a, [128:256) shift b
static __device__ float g_w2l[FDIM * FDIM];
static __device__ float g_w2r[FDIM * FDIM];
static __device__ float g_b2 [FDIM];
static __device__ int   g_cnt[NN];
static __device__ int   g_rowptr[NN + 1];
static __device__ int   g_cursor[NN];
static __device__ int   g_srcs[EMAX];
static __device__ int   g_bsum[NBMAX];
static __device__ int   g_boff[NBMAX + 1];
static __device__ int   g_is64;

// ---------------- edge-index dtype detection --------------------------------
__global__ void k_detect(const void* ei) {
    if (threadIdx.x == 0) {
        const int* p = (const int*)ei;
        g_is64 = (p[1] == 0 && p[3] == 0) ? 1 : 0;
    }
}
__device__ __forceinline__ int edge_val(const void* ei, long long elem) {
    if (g_is64) return reinterpret_cast<const int*>(ei)[2 * elem];
    return reinterpret_cast<const int*>(ei)[elem];
}

// ---------------- zero ------------------------------------------------------
__global__ void k_zero(int n) {
    int i = blockIdx.x * blockDim.x + threadIdx.x;
    if (i < n)   g_cnt[i] = 0;
    if (i < 256) g_bn[i]  = 0.f;
}

// ---------------- CSR build -------------------------------------------------
__global__ void k_hist(const void* __restrict__ ei, int E) {
    int e = blockIdx.x * blockDim.x + threadIdx.x;
    if (e >= E) return;
    atomicAdd(&g_cnt[edge_val(ei, (long long)E + e)], 1);
}

__global__ __launch_bounds__(1024) void k_scan1(int n) {
    __shared__ int warpsum[32];
    int t = threadIdx.x;
    int i = blockIdx.x * 1024 + t;
    int lane = t & 31, wid = t >> 5;
    int v = (i < n) ? g_cnt[i] : 0;
    int x = v;
#pragma unroll
    for (int o = 1; o < 32; o <<= 1) {
        int y = __shfl_up_sync(0xffffffffu, x, o);
        if (lane >= o) x += y;
    }
    if (lane == 31) warpsum[wid] = x;
    __syncthreads();
    if (wid == 0) {
        int s = warpsum[lane];
#pragma unroll
        for (int o = 1; o < 32; o <<= 1) {
            int y = __shfl_up_sync(0xffffffffu, s, o);
            if (lane >= o) s += y;
        }
        warpsum[lane] = s;
    }
    __syncthreads();
    int base = (wid > 0) ? warpsum[wid - 1] : 0;
    int incl = base + x;
    if (i < n) g_rowptr[i] = incl - v;
    if (t == 1023) g_bsum[blockIdx.x] = incl;
}

__global__ void k_scan2(int nb) {
    if (threadIdx.x == 0) {
        int run = 0;
        for (int b = 0; b < nb; b++) { g_boff[b] = run; run += g_bsum[b]; }
        g_boff[nb] = run;
    }
}

__global__ __launch_bounds__(1024) void k_scan3(int n, int nb) {
    int i = blockIdx.x * 1024 + threadIdx.x;
    if (i < n) {
        int v = g_rowptr[i] + g_boff[blockIdx.x];
        g_rowptr[i] = v;
        g_cursor[i] = v;
    }
    if (i == 0) g_rowptr[n] = g_boff[nb];
}

__global__ void k_permute(const void* __restrict__ ei, int E) {
    int e = blockIdx.x * blockDim.x + threadIdx.x;
    if (e >= E) return;
    int sidx = edge_val(ei, e);
    int d    = edge_val(ei, (long long)E + e);
    g_srcs[atomicAdd(&g_cursor[d], 1)] = sidx;
}

// ---------------- aggregation: warp per dst row, gather-sum + mean ----------
template<int SRC>
__global__ void k_agg(const float* __restrict__ xin, int n) {
    int w    = (blockIdx.x * blockDim.x + threadIdx.x) >> 5;
    int lane = threadIdx.x & 31;
    if (w >= n) return;
    const float* buf = (SRC == 0) ? xin : g_h;

    int beg = g_rowptr[w], end = g_rowptr[w + 1];
    float4 acc0 = make_float4(0.f, 0.f, 0.f, 0.f);
    float4 acc1 = acc0;

    for (int i = beg; i < end; i += 32) {
        int idx = (i + lane < end) ? g_srcs[i + lane] : 0;
        int cnt = min(32, end - i);
        int j = 0;
        for (; j + 2 <= cnt; j += 2) {
            int s0 = __shfl_sync(0xffffffffu, idx, j);
            int s1 = __shfl_sync(0xffffffffu, idx, j + 1);
            float4 v0 = reinterpret_cast<const float4*>(buf + (size_t)s0 * FDIM)[lane];
            float4 v1 = reinterpret_cast<const float4*>(buf + (size_t)s1 * FDIM)[lane];
            acc0.x += v0.x; acc0.y += v0.y; acc0.z += v0.z; acc0.w += v0.w;
            acc1.x += v1.x; acc1.y += v1.y; acc1.z += v1.z; acc1.w += v1.w;
        }
        if (j < cnt) {
            int s0 = __shfl_sync(0xffffffffu, idx, j);
            float4 v0 = reinterpret_cast<const float4*>(buf + (size_t)s0 * FDIM)[lane];
            acc0.x += v0.x; acc0.y += v0.y; acc0.z += v0.z; acc0.w += v0.w;
        }
    }
    float inv = (end > beg) ? 1.0f / (float)(end - beg) : 0.f;
    float4 o;
    o.x = (acc0.x + acc1.x) * inv;
    o.y = (acc0.y + acc1.y) * inv;
    o.z = (acc0.z + acc1.z) * inv;
    o.w = (acc0.w + acc1.w) * inv;
    reinterpret_cast<float4*>(g_agg + (size_t)w * FDIM)[lane] = o;
}

// ---------------- packed f32x2 helpers --------------------------------------
__device__ __forceinline__ unsigned long long dup2(float v) {
    unsigned long long r;
    unsigned u = __float_as_uint(v);
    asm("mov.b64 %0, {%1, %1};" : "=l"(r) : "r"(u));
    return r;
}
__device__ __forceinline__ void fma2(unsigned long long& acc,
                                     unsigned long long a, unsigned long long b) {
    asm("fma.rn.f32x2 %0, %1, %2, %0;" : "+l"(acc) : "l"(a), "l"(b));
}
__device__ __forceinline__ void unpack2(unsigned long long p, float& lo, float& hi) {
    unsigned a, b;
    asm("mov.b64 {%0, %1}, %2;" : "=r"(a), "=r"(b) : "l"(p));
    lo = __uint_as_float(a); hi = __uint_as_float(b);
}

// ---------------- fused SAGE linear + bias + L2-norm (+ReLU, +BN stats) -----
// C[64 x 128] per block, 128 threads, 8x8 register tile, pure-FFMA2 inner loop
// (B pairs read as u64x2 directly from smem; A values pre-duplicated at store).
template<int LAYER>
__global__ __launch_bounds__(128)
void k_sage(const float* __restrict__ xin,
            const float* __restrict__ Wl, const float* __restrict__ bl,
            const float* __restrict__ Wr, int n) {
    __shared__ __align__(16) unsigned long long As2[16][64];
    __shared__ __align__(16) float Bs[16][128];
    __shared__ float rowsq[64];
    __shared__ float colstat[256];

    const float* A2  = (LAYER == 1) ? xin : g_h;
    float*       out = (LAYER == 1) ? g_h : g_h2;

    int t  = threadIdx.x;
    int tx = t & 15;
    int ty = t >> 4;
    int row0 = blockIdx.x * 64;

    int lrow = t >> 1;
    int lk   = (t & 1) * 8;
    int grow = row0 + lrow;

    unsigned long long acc[8][4];
#pragma unroll
    for (int i = 0; i < 8; i++)
#pragma unroll
        for (int j = 0; j < 4; j++) acc[i][j] = 0ull;

#pragma unroll 1
    for (int br = 0; br < 2; br++) {
        const float* A = (br == 0) ? g_agg : A2;
        const float* W = (br == 0) ? Wl : Wr;
#pragma unroll 1
        for (int kt = 0; kt < FDIM; kt += 16) {
            float4 a0 = make_float4(0.f,0.f,0.f,0.f), a1 = a0;
            if (grow < n) {
                const float4* ap = reinterpret_cast<const float4*>(
                    A + (size_t)grow * FDIM + kt + lk);
                a0 = ap[0]; a1 = ap[1];
            }
            const float4* wp = reinterpret_cast<const float4*>(W + t * FDIM + kt);
            float4 w0 = wp[0], w1 = wp[1], w2 = wp[2], w3 = wp[3];

            __syncthreads();
            As2[lk+0][lrow] = dup2(a0.x); As2[lk+1][lrow] = dup2(a0.y);
            As2[lk+2][lrow] = dup2(a0.z); As2[lk+3][lrow] = dup2(a0.w);
            As2[lk+4][lrow] = dup2(a1.x); As2[lk+5][lrow] = dup2(a1.y);
            As2[lk+6][lrow] = dup2(a1.z); As2[lk+7][lrow] = dup2(a1.w);

            Bs[ 0][t] = w0.x; Bs[ 1][t] = w0.y; Bs[ 2][t] = w0.z; Bs[ 3][t] = w0.w;
            Bs[ 4][t] = w1.x; Bs[ 5][t] = w1.y; Bs[ 6][t] = w1.z; Bs[ 7][t] = w1.w;
            Bs[ 8][t] = w2.x; Bs[ 9][t] = w2.y; Bs[10][t] = w2.z; Bs[11][t] = w2.w;
            Bs[12][t] = w3.x; Bs[13][t] = w3.y; Bs[14][t] = w3.z; Bs[15][t] = w3.w;
            __syncthreads();

#pragma unroll
            for (int k = 0; k < 16; k++) {
                const ulonglong2* aq =
                    reinterpret_cast<const ulonglong2*>(&As2[k][ty * 8]);
                ulonglong2 aA = aq[0], aB = aq[1], aC = aq[2], aD = aq[3];
                const ulonglong2* bq =
                    reinterpret_cast<const ulonglong2*>(&Bs[k][tx * 8]);
                ulonglong2 b01 = bq[0], b23 = bq[1];
                unsigned long long ad[8] = {aA.x, aA.y, aB.x, aB.y,
                                            aC.x, aC.y, aD.x, aD.y};
                unsigned long long bp[4] = {b01.x, b01.y, b23.x, b23.y};
#pragma unroll
                for (int i = 0; i < 8; i++)
#pragma unroll
                    for (int j = 0; j < 4; j++)
                        fma2(acc[i][j], ad[i], bp[j]);
            }
        }
    }

    // epilogue: bias, per-row L2 norm over the block's full 128 cols
    if (t < 64) rowsq[t] = 0.f;
    if (LAYER == 1) { colstat[t] = 0.f; colstat[t + 128] = 0.f; }
    __syncthreads();

    float bias[8];
#pragma unroll
    for (int j = 0; j < 8; j++) bias[j] = bl[tx * 8 + j];

    float o[8][8];
#pragma unroll
    for (int i = 0; i < 8; i++) {
        float s = 0.f;
#pragma unroll
        for (int j = 0; j < 4; j++) {
            float lo, hi;
            unpack2(acc[i][j], lo, hi);
            lo += bias[2*j]; hi += bias[2*j+1];
            o[i][2*j] = lo; o[i][2*j+1] = hi;
            s = fmaf(lo, lo, s);
            s = fmaf(hi, hi, s);
        }
        atomicAdd(&rowsq[ty * 8 + i], s);
    }
    __syncthreads();

    float cs[8], cq[8];
#pragma unroll
    for (int j = 0; j < 8; j++) { cs[j] = 0.f; cq[j] = 0.f; }

#pragma unroll
    for (int i = 0; i < 8; i++) {
        int r = row0 + ty * 8 + i;
        if (r >= n) continue;
        float inv = 1.0f / fmaxf(sqrtf(rowsq[ty * 8 + i]), 1e-12f);
        float v[8];
#pragma unroll
        for (int j = 0; j < 8; j++) {
            v[j] = o[i][j] * inv;
            if (LAYER == 1) {
                v[j] = fmaxf(v[j], 0.f);           // ReLU
                cs[j] += v[j];
                cq[j] = fmaf(v[j], v[j], cq[j]);   // BN stats
            }
        }
        float4* op = reinterpret_cast<float4*>(out + (size_t)r * FDIM + tx * 8);
        op[0] = make_float4(v[0], v[1], v[2], v[3]);
        op[1] = make_float4(v[4], v[5], v[6], v[7]);
    }

    if (LAYER == 1) {
#pragma unroll
        for (int j = 0; j < 8; j++) {
            atomicAdd(&colstat[tx * 8 + j], cs[j]);
            atomicAdd(&colstat[128 + tx * 8 + j], cq[j]);
        }
        __syncthreads();
        atomicAdd(&g_bn[t],       colstat[t]);
        atomicAdd(&g_bn[t + 128], colstat[t + 128]);
    }
}

// ---------------- BN coefficients + weight folding ---------------------------
__global__ void k_bncoef(const float* __restrict__ gamma,
                         const float* __restrict__ beta, float invn) {
    int t = threadIdx.x;
    float mu  = g_bn[t] * invn;
    float var = g_bn[128 + t] * invn - mu * mu;
    float a = gamma[t] * rsqrtf(fmaxf(var, 0.f) + 1e-5f);
    g_bnab[t]       = a;
    g_bnab[128 + t] = fmaf(-mu, a, beta[t]);
}

// scale layer-2 weight columns by a[k]
__global__ void k_bnfold(const float* __restrict__ W2l,
                         const float* __restrict__ W2r) {
    int i = blockIdx.x * blockDim.x + threadIdx.x;
    if (i >= FDIM * FDIM) return;
    float a = g_bnab[i & (FDIM - 1)];
    g_w2l[i] = W2l[i] * a;
    g_w2r[i] = W2r[i] * a;
}

// bias2' = b2l + (W2l + W2r) @ shift   (one block per output)
__global__ void k_bnbias(const float* __restrict__ W2l,
                         const float* __restrict__ W2r,
                         const float* __restrict__ b2l) {
    __shared__ float red[128];
    int o = blockIdx.x, t = threadIdx.x;
    red[t] = (W2l[o * FDIM + t] + W2r[o * FDIM + t]) * g_bnab[128 + t];
    __syncthreads();
#pragma unroll
    for (int off = 64; off; off >>= 1) {
        if (t < off) red[t] += red[t + off];
        __syncthreads();
    }
    if (t == 0) g_b2[o] = b2l[o] + red[0];
}

// ---------------- FC head: warp per row --------------------------------------
__global__ void k_fc(const float* __restrict__ W, const float* __restrict__ b,
                     float* __restrict__ out, int n) {
    __shared__ __align__(16) float Ws[8 * FDIM];
    int t = threadIdx.x;
    reinterpret_cast<float4*>(Ws)[t] = reinterpret_cast<const float4*>(W)[t];
    __syncthreads();

    int warp = (blockIdx.x * blockDim.x + t) >> 5;
    int lane = t & 31;
    if (warp >= n) return;

    float4 v = reinterpret_cast<const float4*>(g_h2 + (size_t)warp * FDIM)[lane];
    float acc[8];
#pragma unroll
    for (int j = 0; j < 8; j++) {
        float4 w = reinterpret_cast<float4*>(Ws)[j * 32 + lane];
        acc[j] = v.x * w.x + v.y * w.y + v.z * w.z + v.w * w.w;
    }
#pragma unroll
    for (int off = 16; off; off >>= 1)
#pragma unroll
        for (int j = 0; j < 8; j++)
            acc[j] += __shfl_down_sync(0xffffffffu, acc[j], off);
    if (lane == 0) {
#pragma unroll
        for (int j = 0; j < 8; j++)
            out[(size_t)warp * 8 + j] = acc[j] + b[j];
    }
}

// ---------------- launch ------------------------------------------------------
extern "C" void kernel_launch(void* const* d_in, const int* in_sizes, int n_in,
                              void* d_out, int out_size) {
    const float* x   = (const float*)d_in[0];
    const void*  ei  = d_in[1];
    const float* W1l = (const float*)d_in[2];
    const float* b1l = (const float*)d_in[3];
    const float* W1r = (const float*)d_in[4];
    const float* gma = (const float*)d_in[5];
    const float* bta = (const float*)d_in[6];
    const float* W2l = (const float*)d_in[7];
    const float* b2l = (const float*)d_in[8];
    const float* W2r = (const float*)d_in[9];
    const float* Wfc = (const float*)d_in[10];
    const float* bfc = (const float*)d_in[11];
    float* out = (float*)d_out;

    int n  = in_sizes[0] / FDIM;
    int E  = in_sizes[1] / 2;
    int zb = (n + 255) / 256;
    int eb = (E + 255) / 256;
    int gb = (n + 63) / 64;
    int ab = (n * 32 + 255) / 256;
    int fb = (n * 32 + 255) / 256;
    int nb = (n + 1023) / 1024;

    float* w2lp; cudaGetSymbolAddress((void**)&w2lp, g_w2l);
    float* w2rp; cudaGetSymbolAddress((void**)&w2rp, g_w2r);
    float* b2p;  cudaGetSymbolAddress((void**)&b2p,  g_b2);

    k_detect<<<1, 32>>>(ei);
    k_zero<<<zb, 256>>>(n);
    k_hist<<<eb, 256>>>(ei, E);
    k_scan1<<<nb, 1024>>>(n);
    k_scan2<<<1, 32>>>(nb);
    k_scan3<<<nb, 1024>>>(n, nb);
    k_permute<<<eb, 256>>>(ei, E);
    k_agg<0><<<ab, 256>>>(x, n);
    k_sage<1><<<gb, 128>>>(x, W1l, b1l, W1r, n);
    k_bncoef<<<1, 128>>>(gma, bta, 1.0f / (float)n);
    k_bnfold<<<(FDIM * FDIM + 255) / 256, 256>>>(W2l, W2r);
    k_bnbias<<<FDIM, 128>>>(W2l, W2r, b2l);
    k_agg<1><<<ab, 256>>>(x, n);
    k_sage<2><<<gb, 128>>>(x, w2lp, b2p, w2rp, n);
    k_fc<<<fb, 256>>>(Wfc, bfc, out, n);
}

// round 5
// speedup vs baseline: 1.0976x; 1.0976x over previous
#include <cuda_runtime.h>

#define FDIM 128
#define NN   50000
#define EMAX 800000
#define NBMAX 64

// ---------------- scratch (device globals) ----------------------------------
static __device__ float g_agg[(size_t)NN * FDIM];
static __device__ float g_h  [(size_t)NN * FDIM];
static __device__ float g_h2 [(size_t)NN * FDIM];
static __device__ float g_bn [256];    // [0:128) sum, [128:256) sumsq
static __device__ float g_bnab[256];   // [0:128) scale a, [128:256) shift b
static __device__ float g_w2r[FDIM * FDIM];
static __device__ float g_b2 [FDIM];
static __device__ int   g_cnt[NN];
static __device__ int   g_rowptr[NN + 1];
static __device__ int   g_cursor[NN];
static __device__ int   g_srcs[EMAX];
static __device__ int   g_bsum[NBMAX];
static __device__ int   g_boff[NBMAX + 1];
static __device__ int   g_is64;

// ---------------- edge-index dtype detection --------------------------------
__global__ void k_detect(const void* ei) {
    if (threadIdx.x == 0) {
        const int* p = (const int*)ei;
        g_is64 = (p[1] == 0 && p[3] == 0) ? 1 : 0;
    }
}
__device__ __forceinline__ int edge_val(const void* ei, long long elem) {
    if (g_is64) return reinterpret_cast<const int*>(ei)[2 * elem];
    return reinterpret_cast<const int*>(ei)[elem];
}

// ---------------- zero ------------------------------------------------------
__global__ void k_zero(int n) {
    int i = blockIdx.x * blockDim.x + threadIdx.x;
    if (i < n)   g_cnt[i] = 0;
    if (i < 256) g_bn[i]  = 0.f;
}

// ---------------- CSR build -------------------------------------------------
__global__ void k_hist(const void* __restrict__ ei, int E) {
    int e = blockIdx.x * blockDim.x + threadIdx.x;
    if (e >= E) return;
    atomicAdd(&g_cnt[edge_val(ei, (long long)E + e)], 1);
}

__global__ __launch_bounds__(1024) void k_scan1(int n) {
    __shared__ int warpsum[32];
    int t = threadIdx.x;
    int i = blockIdx.x * 1024 + t;
    int lane = t & 31, wid = t >> 5;
    int v = (i < n) ? g_cnt[i] : 0;
    int x = v;
#pragma unroll
    for (int o = 1; o < 32; o <<= 1) {
        int y = __shfl_up_sync(0xffffffffu, x, o);
        if (lane >= o) x += y;
    }
    if (lane == 31) warpsum[wid] = x;
    __syncthreads();
    if (wid == 0) {
        int s = warpsum[lane];
#pragma unroll
        for (int o = 1; o < 32; o <<= 1) {
            int y = __shfl_up_sync(0xffffffffu, s, o);
            if (lane >= o) s += y;
        }
        warpsum[lane] = s;
    }
    __syncthreads();
    int base = (wid > 0) ? warpsum[wid - 1] : 0;
    int incl = base + x;
    if (i < n) g_rowptr[i] = incl - v;
    if (t == 1023) g_bsum[blockIdx.x] = incl;
}

__global__ void k_scan2(int nb) {
    if (threadIdx.x == 0) {
        int run = 0;
        for (int b = 0; b < nb; b++) { g_boff[b] = run; run += g_bsum[b]; }
        g_boff[nb] = run;
    }
}

__global__ __launch_bounds__(1024) void k_scan3(int n, int nb) {
    int i = blockIdx.x * 1024 + threadIdx.x;
    if (i < n) {
        int v = g_rowptr[i] + g_boff[blockIdx.x];
        g_rowptr[i] = v;
        g_cursor[i] = v;
    }
    if (i == 0) g_rowptr[n] = g_boff[nb];
}

__global__ void k_permute(const void* __restrict__ ei, int E) {
    int e = blockIdx.x * blockDim.x + threadIdx.x;
    if (e >= E) return;
    int sidx = edge_val(ei, e);
    int d    = edge_val(ei, (long long)E + e);
    g_srcs[atomicAdd(&g_cursor[d], 1)] = sidx;
}

// ---------------- aggregation: warp per dst row, gather-sum + mean ----------
// BN=1: output = a * mean + b  (per column, only when deg>0), exact BN fold.
template<int BN>
__global__ void k_agg(const float* __restrict__ xin, int n) {
    int w    = (blockIdx.x * blockDim.x + threadIdx.x) >> 5;
    int lane = threadIdx.x & 31;
    if (w >= n) return;
    const float* buf = (BN == 0) ? xin : g_h;

    int beg = g_rowptr[w], end = g_rowptr[w + 1];
    float4 acc0 = make_float4(0.f, 0.f, 0.f, 0.f);
    float4 acc1 = acc0;

    for (int i = beg; i < end; i += 32) {
        int idx = (i + lane < end) ? g_srcs[i + lane] : 0;
        int cnt = min(32, end - i);
        int j = 0;
        for (; j + 2 <= cnt; j += 2) {
            int s0 = __shfl_sync(0xffffffffu, idx, j);
            int s1 = __shfl_sync(0xffffffffu, idx, j + 1);
            float4 v0 = reinterpret_cast<const float4*>(buf + (size_t)s0 * FDIM)[lane];
            float4 v1 = reinterpret_cast<const float4*>(buf + (size_t)s1 * FDIM)[lane];
            acc0.x += v0.x; acc0.y += v0.y; acc0.z += v0.z; acc0.w += v0.w;
            acc1.x += v1.x; acc1.y += v1.y; acc1.z += v1.z; acc1.w += v1.w;
        }
        if (j < cnt) {
            int s0 = __shfl_sync(0xffffffffu, idx, j);
            float4 v0 = reinterpret_cast<const float4*>(buf + (size_t)s0 * FDIM)[lane];
            acc0.x += v0.x; acc0.y += v0.y; acc0.z += v0.z; acc0.w += v0.w;
        }
    }
    float4 o = make_float4(0.f, 0.f, 0.f, 0.f);
    if (end > beg) {
        float inv = 1.0f / (float)(end - beg);
        o.x = (acc0.x + acc1.x) * inv;
        o.y = (acc0.y + acc1.y) * inv;
        o.z = (acc0.z + acc1.z) * inv;
        o.w = (acc0.w + acc1.w) * inv;
        if (BN == 1) {
            float4 a = reinterpret_cast<const float4*>(g_bnab)[lane];
            float4 b = reinterpret_cast<const float4*>(g_bnab)[32 + lane];
            o.x = fmaf(o.x, a.x, b.x);
            o.y = fmaf(o.y, a.y, b.y);
            o.z = fmaf(o.z, a.z, b.z);
            o.w = fmaf(o.w, a.w, b.w);
        }
    }
    reinterpret_cast<float4*>(g_agg + (size_t)w * FDIM)[lane] = o;
}

// ---------------- packed f32x2 helpers --------------------------------------
__device__ __forceinline__ unsigned long long dup2(float v) {
    unsigned long long r;
    unsigned u = __float_as_uint(v);
    asm("mov.b64 %0, {%1, %1};" : "=l"(r) : "r"(u));
    return r;
}
__device__ __forceinline__ void fma2(unsigned long long& acc,
                                     unsigned long long a, unsigned long long b) {
    asm("fma.rn.f32x2 %0, %1, %2, %0;" : "+l"(acc) : "l"(a), "l"(b));
}
__device__ __forceinline__ void unpack2(unsigned long long p, float& lo, float& hi) {
    unsigned a, b;
    asm("mov.b64 {%0, %1}, %2;" : "=r"(a), "=r"(b) : "l"(p));
    lo = __uint_as_float(a); hi = __uint_as_float(b);
}

// ---------------- fused SAGE linear + bias + L2-norm (+ReLU, +BN stats) -----
// C[64 x 128] per block, 128 threads, 8x8 register tile, FFMA2 inner loop,
// register-prefetch software pipeline over 16 tiles (2 branches x 8 k-tiles).
template<int LAYER>
__global__ __launch_bounds__(128)
void k_sage(const float* __restrict__ xin,
            const float* __restrict__ Wl, const float* __restrict__ bl,
            const float* __restrict__ Wr, int n) {
    __shared__ __align__(16) float As[16][64];
    __shared__ __align__(16) float Bs[16][128];
    __shared__ float rowsq[64];
    __shared__ float colstat[256];

    const float* A2  = (LAYER == 1) ? xin : g_h;
    float*       out = (LAYER == 1) ? g_h : g_h2;

    int t  = threadIdx.x;
    int tx = t & 15;
    int ty = t >> 4;
    int row0 = blockIdx.x * 64;

    int lrow = t >> 1;
    int lk   = (t & 1) * 8;
    int grow = row0 + lrow;
    bool rok = (grow < n);

    unsigned long long acc[8][4];
#pragma unroll
    for (int i = 0; i < 8; i++)
#pragma unroll
        for (int j = 0; j < 4; j++) acc[i][j] = 0ull;

    float4 pa0, pa1, pw0, pw1, pw2, pw3;

    // prefetch tile 0
    {
        const float* A = g_agg;
        const float* W = Wl;
        pa0 = make_float4(0.f,0.f,0.f,0.f); pa1 = pa0;
        if (rok) {
            const float4* ap = reinterpret_cast<const float4*>(
                A + (size_t)grow * FDIM + lk);
            pa0 = ap[0]; pa1 = ap[1];
        }
        const float4* wp = reinterpret_cast<const float4*>(W + t * FDIM);
        pw0 = wp[0]; pw1 = wp[1]; pw2 = wp[2]; pw3 = wp[3];
    }

#pragma unroll 1
    for (int tt = 0; tt < 16; tt++) {
        __syncthreads();
        As[lk+0][lrow] = pa0.x; As[lk+1][lrow] = pa0.y;
        As[lk+2][lrow] = pa0.z; As[lk+3][lrow] = pa0.w;
        As[lk+4][lrow] = pa1.x; As[lk+5][lrow] = pa1.y;
        As[lk+6][lrow] = pa1.z; As[lk+7][lrow] = pa1.w;

        Bs[ 0][t] = pw0.x; Bs[ 1][t] = pw0.y; Bs[ 2][t] = pw0.z; Bs[ 3][t] = pw0.w;
        Bs[ 4][t] = pw1.x; Bs[ 5][t] = pw1.y; Bs[ 6][t] = pw1.z; Bs[ 7][t] = pw1.w;
        Bs[ 8][t] = pw2.x; Bs[ 9][t] = pw2.y; Bs[10][t] = pw2.z; Bs[11][t] = pw2.w;
        Bs[12][t] = pw3.x; Bs[13][t] = pw3.y; Bs[14][t] = pw3.z; Bs[15][t] = pw3.w;
        __syncthreads();

        if (tt < 15) {  // prefetch next tile; overlaps the inner loop below
            int nt = tt + 1;
            int br = nt >> 3;
            int kt = (nt & 7) << 4;
            const float* A = (br == 0) ? g_agg : A2;
            const float* W = (br == 0) ? Wl : Wr;
            pa0 = make_float4(0.f,0.f,0.f,0.f); pa1 = pa0;
            if (rok) {
                const float4* ap = reinterpret_cast<const float4*>(
                    A + (size_t)grow * FDIM + kt + lk);
                pa0 = ap[0]; pa1 = ap[1];
            }
            const float4* wp = reinterpret_cast<const float4*>(W + t * FDIM + kt);
            pw0 = wp[0]; pw1 = wp[1]; pw2 = wp[2]; pw3 = wp[3];
        }

#pragma unroll
        for (int k = 0; k < 16; k++) {
            const float4* aq = reinterpret_cast<const float4*>(&As[k][ty * 8]);
            float4 p0 = aq[0], p1 = aq[1];
            const ulonglong2* bq =
                reinterpret_cast<const ulonglong2*>(&Bs[k][tx * 8]);
            ulonglong2 b01 = bq[0], b23 = bq[1];
            unsigned long long bp[4] = {b01.x, b01.y, b23.x, b23.y};
            float aa[8] = {p0.x,p0.y,p0.z,p0.w,p1.x,p1.y,p1.z,p1.w};
#pragma unroll
            for (int i = 0; i < 8; i++) {
                unsigned long long ad = dup2(aa[i]);
#pragma unroll
                for (int j = 0; j < 4; j++) fma2(acc[i][j], ad, bp[j]);
            }
        }
    }

    // epilogue: bias, per-row L2 norm over the block's full 128 cols
    if (t < 64) rowsq[t] = 0.f;
    if (LAYER == 1) { colstat[t] = 0.f; colstat[t + 128] = 0.f; }
    __syncthreads();

    float bias[8];
#pragma unroll
    for (int j = 0; j < 8; j++) bias[j] = bl[tx * 8 + j];

    float o[8][8];
#pragma unroll
    for (int i = 0; i < 8; i++) {
        float s = 0.f;
#pragma unroll
        for (int j = 0; j < 4; j++) {
            float lo, hi;
            unpack2(acc[i][j], lo, hi);
            lo += bias[2*j]; hi += bias[2*j+1];
            o[i][2*j] = lo; o[i][2*j+1] = hi;
            s = fmaf(lo, lo, s);
            s = fmaf(hi, hi, s);
        }
        atomicAdd(&rowsq[ty * 8 + i], s);
    }
    __syncthreads();

    float cs[8], cq[8];
#pragma unroll
    for (int j = 0; j < 8; j++) { cs[j] = 0.f; cq[j] = 0.f; }

#pragma unroll
    for (int i = 0; i < 8; i++) {
        int r = row0 + ty * 8 + i;
        if (r >= n) continue;
        float inv = 1.0f / fmaxf(sqrtf(rowsq[ty * 8 + i]), 1e-12f);
        float v[8];
#pragma unroll
        for (int j = 0; j < 8; j++) {
            v[j] = o[i][j] * inv;
            if (LAYER == 1) {
                v[j] = fmaxf(v[j], 0.f);           // ReLU
                cs[j] += v[j];
                cq[j] = fmaf(v[j], v[j], cq[j]);   // BN stats
            }
        }
        float4* op = reinterpret_cast<float4*>(out + (size_t)r * FDIM + tx * 8);
        op[0] = make_float4(v[0], v[1], v[2], v[3]);
        op[1] = make_float4(v[4], v[5], v[6], v[7]);
    }

    if (LAYER == 1) {
#pragma unroll
        for (int j = 0; j < 8; j++) {
            atomicAdd(&colstat[tx * 8 + j], cs[j]);
            atomicAdd(&colstat[128 + tx * 8 + j], cq[j]);
        }
        __syncthreads();
        atomicAdd(&g_bn[t],       colstat[t]);
        atomicAdd(&g_bn[t + 128], colstat[t + 128]);
    }
}

// ---------------- BN coefficients + root-branch weight folding ---------------
__global__ void k_bncoef(const float* __restrict__ gamma,
                         const float* __restrict__ beta, float invn) {
    int t = threadIdx.x;
    float mu  = g_bn[t] * invn;
    float var = g_bn[128 + t] * invn - mu * mu;
    float a = gamma[t] * rsqrtf(fmaxf(var, 0.f) + 1e-5f);
    g_bnab[t]       = a;
    g_bnab[128 + t] = fmaf(-mu, a, beta[t]);
}

// fold scale into root-branch weights: W2r' = W2r * a[col]
__global__ void k_bnfold(const float* __restrict__ W2r) {
    int i = blockIdx.x * blockDim.x + threadIdx.x;
    if (i >= FDIM * FDIM) return;
    g_w2r[i] = W2r[i] * g_bnab[i & (FDIM - 1)];
}

// bias2' = b2l + W2r @ shift   (one block per output; agg branch shift is
// applied exactly inside k_agg<1> with deg>0 gating)
__global__ void k_bnbias(const float* __restrict__ W2r,
                         const float* __restrict__ b2l) {
    __shared__ float red[128];
    int o = blockIdx.x, t = threadIdx.x;
    red[t] = W2r[o * FDIM + t] * g_bnab[128 + t];
    __syncthreads();
#pragma unroll
    for (int off = 64; off; off >>= 1) {
        if (t < off) red[t] += red[t + off];
        __syncthreads();
    }
    if (t == 0) g_b2[o] = b2l[o] + red[0];
}

// ---------------- FC head: warp per row --------------------------------------
__global__ void k_fc(const float* __restrict__ W, const float* __restrict__ b,
                     float* __restrict__ out, int n) {
    __shared__ __align__(16) float Ws[8 * FDIM];
    int t = threadIdx.x;
    reinterpret_cast<float4*>(Ws)[t] = reinterpret_cast<const float4*>(W)[t];
    __syncthreads();

    int warp = (blockIdx.x * blockDim.x + t) >> 5;
    int lane = t & 31;
    if (warp >= n) return;

    float4 v = reinterpret_cast<const float4*>(g_h2 + (size_t)warp * FDIM)[lane];
    float acc[8];
#pragma unroll
    for (int j = 0; j < 8; j++) {
        float4 w = reinterpret_cast<float4*>(Ws)[j * 32 + lane];
        acc[j] = v.x * w.x + v.y * w.y + v.z * w.z + v.w * w.w;
    }
#pragma unroll
    for (int off = 16; off; off >>= 1)
#pragma unroll
        for (int j = 0; j < 8; j++)
            acc[j] += __shfl_down_sync(0xffffffffu, acc[j], off);
    if (lane == 0) {
#pragma unroll
        for (int j = 0; j < 8; j++)
            out[(size_t)warp * 8 + j] = acc[j] + b[j];
    }
}

// ---------------- launch ------------------------------------------------------
extern "C" void kernel_launch(void* const* d_in, const int* in_sizes, int n_in,
                              void* d_out, int out_size) {
    const float* x   = (const float*)d_in[0];
    const void*  ei  = d_in[1];
    const float* W1l = (const float*)d_in[2];
    const float* b1l = (const float*)d_in[3];
    const float* W1r = (const float*)d_in[4];
    const float* gma = (const float*)d_in[5];
    const float* bta = (const float*)d_in[6];
    const float* W2l = (const float*)d_in[7];
    const float* b2l = (const float*)d_in[8];
    const float* W2r = (const float*)d_in[9];
    const float* Wfc = (const float*)d_in[10];
    const float* bfc = (const float*)d_in[11];
    float* out = (float*)d_out;

    int n  = in_sizes[0] / FDIM;
    int E  = in_sizes[1] / 2;
    int zb = (n + 255) / 256;
    int eb = (E + 255) / 256;
    int gb = (n + 63) / 64;
    int ab = (n * 32 + 255) / 256;
    int fb = (n * 32 + 255) / 256;
    int nb = (n + 1023) / 1024;

    float* w2rp; cudaGetSymbolAddress((void**)&w2rp, g_w2r);
    float* b2p;  cudaGetSymbolAddress((void**)&b2p,  g_b2);

    k_detect<<<1, 32>>>(ei);
    k_zero<<<zb, 256>>>(n);
    k_hist<<<eb, 256>>>(ei, E);
    k_scan1<<<nb, 1024>>>(n);
    k_scan2<<<1, 32>>>(nb);
    k_scan3<<<nb, 1024>>>(n, nb);
    k_permute<<<eb, 256>>>(ei, E);
    k_agg<0><<<ab, 256>>>(x, n);
    k_sage<1><<<gb, 128>>>(x, W1l, b1l, W1r, n);
    k_bncoef<<<1, 128>>>(gma, bta, 1.0f / (float)n);
    k_bnfold<<<(FDIM * FDIM + 255) / 256, 256>>>(W2r);
    k_bnbias<<<FDIM, 128>>>(W2r, b2l);
    k_agg<1><<<ab, 256>>>(x, n);
    k_sage<2><<<gb, 128>>>(x, W2l, b2p, w2rp, n);
    k_fc<<<fb, 256>>>(Wfc, bfc, out, n);
}

// round 6
// speedup vs baseline: 1.6423x; 1.4962x over previous
#include <cuda_runtime.h>
#include <cuda_bf16.h>

#define FDIM 128
#define NN   50000
#define EMAX 800000
#define NBMAX 64

// ---------------- scratch (device globals) ----------------------------------
static __device__ float g_agg[(size_t)NN * FDIM];
static __device__ float g_h  [(size_t)NN * FDIM];
static __device__ float g_h2 [(size_t)NN * FDIM];
static __device__ float g_bn [256];    // [0:128) sum, [128:256) sumsq
static __device__ float g_bnab[256];   // [0:128) scale a, [128:256) shift b
static __device__ float g_w2r[FDIM * FDIM];
static __device__ float g_b2 [FDIM];
static __device__ int   g_cnt[NN];
static __device__ int   g_rowptr[NN + 1];
static __device__ int   g_cursor[NN];
static __device__ int   g_srcs[EMAX];
static __device__ int   g_bsum[NBMAX];
static __device__ int   g_boff[NBMAX + 1];
static __device__ int   g_is64;

// ---------------- edge-index dtype detection --------------------------------
__global__ void k_detect(const void* ei) {
    if (threadIdx.x == 0) {
        const int* p = (const int*)ei;
        g_is64 = (p[1] == 0 && p[3] == 0) ? 1 : 0;
    }
}
__device__ __forceinline__ int edge_val(const void* ei, long long elem) {
    if (g_is64) return reinterpret_cast<const int*>(ei)[2 * elem];
    return reinterpret_cast<const int*>(ei)[elem];
}

// ---------------- zero ------------------------------------------------------
__global__ void k_zero(int n) {
    int i = blockIdx.x * blockDim.x + threadIdx.x;
    if (i < n)   g_cnt[i] = 0;
    if (i < 256) g_bn[i]  = 0.f;
}

// ---------------- CSR build -------------------------------------------------
__global__ void k_hist(const void* __restrict__ ei, int E) {
    int e = blockIdx.x * blockDim.x + threadIdx.x;
    if (e >= E) return;
    atomicAdd(&g_cnt[edge_val(ei, (long long)E + e)], 1);
}

__global__ __launch_bounds__(1024) void k_scan1(int n) {
    __shared__ int warpsum[32];
    int t = threadIdx.x;
    int i = blockIdx.x * 1024 + t;
    int lane = t & 31, wid = t >> 5;
    int v = (i < n) ? g_cnt[i] : 0;
    int x = v;
#pragma unroll
    for (int o = 1; o < 32; o <<= 1) {
        int y = __shfl_up_sync(0xffffffffu, x, o);
        if (lane >= o) x += y;
    }
    if (lane == 31) warpsum[wid] = x;
    __syncthreads();
    if (wid == 0) {
        int s = warpsum[lane];
#pragma unroll
        for (int o = 1; o < 32; o <<= 1) {
            int y = __shfl_up_sync(0xffffffffu, s, o);
            if (lane >= o) s += y;
        }
        warpsum[lane] = s;
    }
    __syncthreads();
    int base = (wid > 0) ? warpsum[wid - 1] : 0;
    int incl = base + x;
    if (i < n) g_rowptr[i] = incl - v;
    if (t == 1023) g_bsum[blockIdx.x] = incl;
}

__global__ void k_scan2(int nb) {
    if (threadIdx.x == 0) {
        int run = 0;
        for (int b = 0; b < nb; b++) { g_boff[b] = run; run += g_bsum[b]; }
        g_boff[nb] = run;
    }
}

__global__ __launch_bounds__(1024) void k_scan3(int n, int nb) {
    int i = blockIdx.x * 1024 + threadIdx.x;
    if (i < n) {
        int v = g_rowptr[i] + g_boff[blockIdx.x];
        g_rowptr[i] = v;
        g_cursor[i] = v;
    }
    if (i == 0) g_rowptr[n] = g_boff[nb];
}

__global__ void k_permute(const void* __restrict__ ei, int E) {
    int e = blockIdx.x * blockDim.x + threadIdx.x;
    if (e >= E) return;
    int sidx = edge_val(ei, e);
    int d    = edge_val(ei, (long long)E + e);
    g_srcs[atomicAdd(&g_cursor[d], 1)] = sidx;
}

// ---------------- aggregation: warp per dst row, gather-sum + mean ----------
// BN=1: output = a * mean + b  (per column, only when deg>0), exact BN fold.
template<int BN>
__global__ void k_agg(const float* __restrict__ xin, int n) {
    int w    = (blockIdx.x * blockDim.x + threadIdx.x) >> 5;
    int lane = threadIdx.x & 31;
    if (w >= n) return;
    const float* buf = (BN == 0) ? xin : g_h;

    int beg = g_rowptr[w], end = g_rowptr[w + 1];
    float4 acc0 = make_float4(0.f, 0.f, 0.f, 0.f);
    float4 acc1 = acc0;

    for (int i = beg; i < end; i += 32) {
        int idx = (i + lane < end) ? g_srcs[i + lane] : 0;
        int cnt = min(32, end - i);
        int j = 0;
        for (; j + 2 <= cnt; j += 2) {
            int s0 = __shfl_sync(0xffffffffu, idx, j);
            int s1 = __shfl_sync(0xffffffffu, idx, j + 1);
            float4 v0 = reinterpret_cast<const float4*>(buf + (size_t)s0 * FDIM)[lane];
            float4 v1 = reinterpret_cast<const float4*>(buf + (size_t)s1 * FDIM)[lane];
            acc0.x += v0.x; acc0.y += v0.y; acc0.z += v0.z; acc0.w += v0.w;
            acc1.x += v1.x; acc1.y += v1.y; acc1.z += v1.z; acc1.w += v1.w;
        }
        if (j < cnt) {
            int s0 = __shfl_sync(0xffffffffu, idx, j);
            float4 v0 = reinterpret_cast<const float4*>(buf + (size_t)s0 * FDIM)[lane];
            acc0.x += v0.x; acc0.y += v0.y; acc0.z += v0.z; acc0.w += v0.w;
        }
    }
    float4 o = make_float4(0.f, 0.f, 0.f, 0.f);
    if (end > beg) {
        float inv = 1.0f / (float)(end - beg);
        o.x = (acc0.x + acc1.x) * inv;
        o.y = (acc0.y + acc1.y) * inv;
        o.z = (acc0.z + acc1.z) * inv;
        o.w = (acc0.w + acc1.w) * inv;
        if (BN == 1) {
            float4 a = reinterpret_cast<const float4*>(g_bnab)[lane];
            float4 b = reinterpret_cast<const float4*>(g_bnab)[32 + lane];
            o.x = fmaf(o.x, a.x, b.x);
            o.y = fmaf(o.y, a.y, b.y);
            o.z = fmaf(o.z, a.z, b.z);
            o.w = fmaf(o.w, a.w, b.w);
        }
    }
    reinterpret_cast<float4*>(g_agg + (size_t)w * FDIM)[lane] = o;
}

// ---------------- bf16 split helpers ----------------------------------------
__device__ __forceinline__ unsigned bpack(__nv_bfloat16 a, __nv_bfloat16 b) {
    __nv_bfloat162 v; v.x = a; v.y = b;
    return *reinterpret_cast<unsigned*>(&v);
}
__device__ __forceinline__ void split2(float x, float y,
                                       unsigned& hi, unsigned& lo) {
    __nv_bfloat16 hx = __float2bfloat16(x);
    __nv_bfloat16 hy = __float2bfloat16(y);
    float rx = x - __bfloat162float(hx);
    float ry = y - __bfloat162float(hy);
    hi = bpack(hx, hy);
    lo = bpack(__float2bfloat16(rx), __float2bfloat16(ry));
}
__device__ __forceinline__ void mma16816(float* c, const unsigned* a,
                                         const unsigned* b) {
    asm volatile(
        "mma.sync.aligned.m16n8k16.row.col.f32.bf16.bf16.f32 "
        "{%0,%1,%2,%3}, {%4,%5,%6,%7}, {%8,%9}, {%0,%1,%2,%3};"
        : "+f"(c[0]), "+f"(c[1]), "+f"(c[2]), "+f"(c[3])
        : "r"(a[0]), "r"(a[1]), "r"(a[2]), "r"(a[3]), "r"(b[0]), "r"(b[1]));
}

// ---------------- tensor-core SAGE linear + bias + L2-norm (+ReLU, BN stats)
// C[64x128] per block, 256 threads (8 warps: 2 row x 4 col), warp tile 32x32
// = 2x4 m16n8k16 tiles. bf16 hi/lo split, 3 MMAs per tile (~1e-5 rel error).
// K = 256 in 8 chunks of 32, register-prefetch pipeline.
#define SSTRIDE 20   // u32 row stride: bank = 20*g + tig is bijective per warp
template<int LAYER>
__global__ __launch_bounds__(256)
void k_sage_tc(const float* __restrict__ xin,
               const float* __restrict__ Wl, const float* __restrict__ bl,
               const float* __restrict__ Wr, int n) {
    __shared__ unsigned As_hi[64 * SSTRIDE], As_lo[64 * SSTRIDE];
    __shared__ unsigned Bs_hi[128 * SSTRIDE], Bs_lo[128 * SSTRIDE];
    __shared__ float rowsq[64];
    __shared__ float colstat[256];

    const float* A2  = (LAYER == 1) ? xin : g_h;
    float*       out = (LAYER == 1) ? g_h : g_h2;

    int t    = threadIdx.x;
    int lane = t & 31;
    int w    = t >> 5;
    int g    = lane >> 2;
    int tig  = lane & 3;
    int wr   = w >> 2;       // 0..1 (row half)
    int wc   = w & 3;        // 0..3 (col quarter)
    int row0 = blockIdx.x * 64;

    // loader roles
    int arow = t >> 2;            // 0..63
    int akv  = (t * 2) & 7;       // {0,2,4,6}: loads kvec akv, akv+1
    int brow = t >> 1;            // 0..127
    int bkv  = (t * 4) & 7;       // {0,4}: loads kvec bkv..bkv+3
    int agrow = row0 + arow;
    bool aok = (agrow < n);

    if (t < 64) rowsq[t] = 0.f;
    colstat[t] = 0.f;

    float acc[2][4][4];
#pragma unroll
    for (int i = 0; i < 2; i++)
#pragma unroll
        for (int j = 0; j < 4; j++)
#pragma unroll
            for (int l = 0; l < 4; l++) acc[i][j][l] = 0.f;

    float4 pa[2], pb[4];
    {   // prefetch chunk 0: branch 0 (agg, Wl), kbase 0
#pragma unroll
        for (int u = 0; u < 2; u++) {
            pa[u] = make_float4(0.f, 0.f, 0.f, 0.f);
            if (aok)
                pa[u] = *reinterpret_cast<const float4*>(
                    g_agg + (size_t)agrow * FDIM + (akv + u) * 4);
        }
#pragma unroll
        for (int u = 0; u < 4; u++)
            pb[u] = *reinterpret_cast<const float4*>(
                Wl + brow * FDIM + (bkv + u) * 4);
    }

#pragma unroll 1
    for (int tt = 0; tt < 8; tt++) {
        __syncthreads();
        // convert + store current chunk to smem
#pragma unroll
        for (int u = 0; u < 2; u++) {
            unsigned h0, l0, h1, l1;
            split2(pa[u].x, pa[u].y, h0, l0);
            split2(pa[u].z, pa[u].w, h1, l1);
            int c0 = arow * SSTRIDE + (akv + u) * 2;
            As_hi[c0] = h0; As_hi[c0 + 1] = h1;
            As_lo[c0] = l0; As_lo[c0 + 1] = l1;
        }
#pragma unroll
        for (int u = 0; u < 4; u++) {
            unsigned h0, l0, h1, l1;
            split2(pb[u].x, pb[u].y, h0, l0);
            split2(pb[u].z, pb[u].w, h1, l1);
            int c0 = brow * SSTRIDE + (bkv + u) * 2;
            Bs_hi[c0] = h0; Bs_hi[c0 + 1] = h1;
            Bs_lo[c0] = l0; Bs_lo[c0 + 1] = l1;
        }
        __syncthreads();

        if (tt < 7) {   // prefetch next chunk (overlaps MMA below)
            int nt = tt + 1;
            const float* A = (nt & 4) ? A2 : g_agg;
            const float* W = (nt & 4) ? Wr : Wl;
            int kbase = (nt & 3) * 32;
#pragma unroll
            for (int u = 0; u < 2; u++) {
                pa[u] = make_float4(0.f, 0.f, 0.f, 0.f);
                if (aok)
                    pa[u] = *reinterpret_cast<const float4*>(
                        A + (size_t)agrow * FDIM + kbase + (akv + u) * 4);
            }
#pragma unroll
            for (int u = 0; u < 4; u++)
                pb[u] = *reinterpret_cast<const float4*>(
                    W + brow * FDIM + kbase + (bkv + u) * 4);
        }

        // compute: 2 x k16 steps
#pragma unroll
        for (int kt = 0; kt < 2; kt++) {
            unsigned bh[4][2], bl2[4][2];
#pragma unroll
            for (int ct = 0; ct < 4; ct++) {
                int bro = (wc * 32 + ct * 8 + g) * SSTRIDE + kt * 8;
                bh[ct][0]  = Bs_hi[bro + tig];
                bh[ct][1]  = Bs_hi[bro + tig + 4];
                bl2[ct][0] = Bs_lo[bro + tig];
                bl2[ct][1] = Bs_lo[bro + tig + 4];
            }
#pragma unroll
            for (int rt = 0; rt < 2; rt++) {
                int ar0 = (wr * 32 + rt * 16 + g) * SSTRIDE + kt * 8;
                int ar1 = ar0 + 8 * SSTRIDE;
                unsigned ah[4] = {As_hi[ar0 + tig], As_hi[ar1 + tig],
                                  As_hi[ar0 + tig + 4], As_hi[ar1 + tig + 4]};
                unsigned al[4] = {As_lo[ar0 + tig], As_lo[ar1 + tig],
                                  As_lo[ar0 + tig + 4], As_lo[ar1 + tig + 4]};
#pragma unroll
                for (int ct = 0; ct < 4; ct++) {
                    mma16816(acc[rt][ct], ah, bh[ct]);
                    mma16816(acc[rt][ct], ah, bl2[ct]);
                    mma16816(acc[rt][ct], al, bh[ct]);
                }
            }
        }
    }

    // ---------- epilogue ----------
    float bias[4][2];
#pragma unroll
    for (int ct = 0; ct < 4; ct++) {
        int col = wc * 32 + ct * 8 + 2 * tig;
        bias[ct][0] = bl[col];
        bias[ct][1] = bl[col + 1];
    }
#pragma unroll
    for (int rt = 0; rt < 2; rt++)
#pragma unroll
        for (int ct = 0; ct < 4; ct++) {
            acc[rt][ct][0] += bias[ct][0];
            acc[rt][ct][1] += bias[ct][1];
            acc[rt][ct][2] += bias[ct][0];
            acc[rt][ct][3] += bias[ct][1];
        }

    // row L2 sums: reduce over tig (lanes sharing a row), then smem atomics
#pragma unroll
    for (int rt = 0; rt < 2; rt++)
#pragma unroll
        for (int h = 0; h < 2; h++) {
            float s = 0.f;
#pragma unroll
            for (int ct = 0; ct < 4; ct++) {
                float v0 = acc[rt][ct][2 * h], v1 = acc[rt][ct][2 * h + 1];
                s = fmaf(v0, v0, s);
                s = fmaf(v1, v1, s);
            }
            s += __shfl_xor_sync(0xffffffffu, s, 1);
            s += __shfl_xor_sync(0xffffffffu, s, 2);
            if (tig == 0)
                atomicAdd(&rowsq[wr * 32 + rt * 16 + g + 8 * h], s);
        }
    __syncthreads();

    float cs[4][2], cq[4][2];
#pragma unroll
    for (int ct = 0; ct < 4; ct++) {
        cs[ct][0] = cs[ct][1] = 0.f;
        cq[ct][0] = cq[ct][1] = 0.f;
    }

#pragma unroll
    for (int rt = 0; rt < 2; rt++)
#pragma unroll
        for (int h = 0; h < 2; h++) {
            int rl = wr * 32 + rt * 16 + g + 8 * h;
            int r  = row0 + rl;
            if (r >= n) continue;
            float inv = 1.0f / fmaxf(sqrtf(rowsq[rl]), 1e-12f);
#pragma unroll
            for (int ct = 0; ct < 4; ct++) {
                float v0 = acc[rt][ct][2 * h] * inv;
                float v1 = acc[rt][ct][2 * h + 1] * inv;
                if (LAYER == 1) {
                    v0 = fmaxf(v0, 0.f);
                    v1 = fmaxf(v1, 0.f);
                    cs[ct][0] += v0; cs[ct][1] += v1;
                    cq[ct][0] = fmaf(v0, v0, cq[ct][0]);
                    cq[ct][1] = fmaf(v1, v1, cq[ct][1]);
                }
                int col = wc * 32 + ct * 8 + 2 * tig;
                *reinterpret_cast<float2*>(out + (size_t)r * FDIM + col) =
                    make_float2(v0, v1);
            }
        }

    if (LAYER == 1) {
        // reduce BN col stats over g (lanes sharing cols), then smem atomics
#pragma unroll
        for (int ct = 0; ct < 4; ct++)
#pragma unroll
            for (int j = 0; j < 2; j++) {
#pragma unroll
                for (int o = 4; o < 32; o <<= 1) {
                    cs[ct][j] += __shfl_xor_sync(0xffffffffu, cs[ct][j], o);
                    cq[ct][j] += __shfl_xor_sync(0xffffffffu, cq[ct][j], o);
                }
            }
        if (g == 0) {
#pragma unroll
            for (int ct = 0; ct < 4; ct++) {
                int col = wc * 32 + ct * 8 + 2 * tig;
                atomicAdd(&colstat[col],           cs[ct][0]);
                atomicAdd(&colstat[col + 1],       cs[ct][1]);
                atomicAdd(&colstat[128 + col],     cq[ct][0]);
                atomicAdd(&colstat[128 + col + 1], cq[ct][1]);
            }
        }
        __syncthreads();
        atomicAdd(&g_bn[t], colstat[t]);
    }
}

// ---------------- BN coefficients + root-branch weight folding ---------------
__global__ void k_bncoef(const float* __restrict__ gamma,
                         const float* __restrict__ beta, float invn) {
    int t = threadIdx.x;
    float mu  = g_bn[t] * invn;
    float var = g_bn[128 + t] * invn - mu * mu;
    float a = gamma[t] * rsqrtf(fmaxf(var, 0.f) + 1e-5f);
    g_bnab[t]       = a;
    g_bnab[128 + t] = fmaf(-mu, a, beta[t]);
}

__global__ void k_bnfold(const float* __restrict__ W2r) {
    int i = blockIdx.x * blockDim.x + threadIdx.x;
    if (i >= FDIM * FDIM) return;
    g_w2r[i] = W2r[i] * g_bnab[i & (FDIM - 1)];
}

__global__ void k_bnbias(const float* __restrict__ W2r,
                         const float* __restrict__ b2l) {
    __shared__ float red[128];
    int o = blockIdx.x, t = threadIdx.x;
    red[t] = W2r[o * FDIM + t] * g_bnab[128 + t];
    __syncthreads();
#pragma unroll
    for (int off = 64; off; off >>= 1) {
        if (t < off) red[t] += red[t + off];
        __syncthreads();
    }
    if (t == 0) g_b2[o] = b2l[o] + red[0];
}

// ---------------- FC head: warp per row --------------------------------------
__global__ void k_fc(const float* __restrict__ W, const float* __restrict__ b,
                     float* __restrict__ out, int n) {
    __shared__ __align__(16) float Ws[8 * FDIM];
    int t = threadIdx.x;
    reinterpret_cast<float4*>(Ws)[t] = reinterpret_cast<const float4*>(W)[t];
    __syncthreads();

    int warp = (blockIdx.x * blockDim.x + t) >> 5;
    int lane = t & 31;
    if (warp >= n) return;

    float4 v = reinterpret_cast<const float4*>(g_h2 + (size_t)warp * FDIM)[lane];
    float acc[8];
#pragma unroll
    for (int j = 0; j < 8; j++) {
        float4 w = reinterpret_cast<float4*>(Ws)[j * 32 + lane];
        acc[j] = v.x * w.x + v.y * w.y + v.z * w.z + v.w * w.w;
    }
#pragma unroll
    for (int off = 16; off; off >>= 1)
#pragma unroll
        for (int j = 0; j < 8; j++)
            acc[j] += __shfl_down_sync(0xffffffffu, acc[j], off);
    if (lane == 0) {
#pragma unroll
        for (int j = 0; j < 8; j++)
            out[(size_t)warp * 8 + j] = acc[j] + b[j];
    }
}

// ---------------- launch ------------------------------------------------------
extern "C" void kernel_launch(void* const* d_in, const int* in_sizes, int n_in,
                              void* d_out, int out_size) {
    const float* x   = (const float*)d_in[0];
    const void*  ei  = d_in[1];
    const float* W1l = (const float*)d_in[2];
    const float* b1l = (const float*)d_in[3];
    const float* W1r = (const float*)d_in[4];
    const float* gma = (const float*)d_in[5];
    const float* bta = (const float*)d_in[6];
    const float* W2l = (const float*)d_in[7];
    const float* b2l = (const float*)d_in[8];
    const float* W2r = (const float*)d_in[9];
    const float* Wfc = (const float*)d_in[10];
    const float* bfc = (const float*)d_in[11];
    float* out = (float*)d_out;

    int n  = in_sizes[0] / FDIM;
    int E  = in_sizes[1] / 2;
    int zb = (n + 255) / 256;
    int eb = (E + 255) / 256;
    int gb = (n + 63) / 64;
    int ab = (n * 32 + 255) / 256;
    int fb = (n * 32 + 255) / 256;
    int nb = (n + 1023) / 1024;

    float* w2rp; cudaGetSymbolAddress((void**)&w2rp, g_w2r);
    float* b2p;  cudaGetSymbolAddress((void**)&b2p,  g_b2);

    k_detect<<<1, 32>>>(ei);
    k_zero<<<zb, 256>>>(n);
    k_hist<<<eb, 256>>>(ei, E);
    k_scan1<<<nb, 1024>>>(n);
    k_scan2<<<1, 32>>>(nb);
    k_scan3<<<nb, 1024>>>(n, nb);
    k_permute<<<eb, 256>>>(ei, E);
    k_agg<0><<<ab, 256>>>(x, n);
    k_sage_tc<1><<<gb, 256>>>(x, W1l, b1l, W1r, n);
    k_bncoef<<<1, 128>>>(gma, bta, 1.0f / (float)n);
    k_bnfold<<<(FDIM * FDIM + 255) / 256, 256>>>(W2r);
    k_bnbias<<<FDIM, 128>>>(W2r, b2l);
    k_agg<1><<<ab, 256>>>(x, n);
    k_sage_tc<2><<<gb, 256>>>(x, W2l, b2p, w2rp, n);
    k_fc<<<fb, 256>>>(Wfc, bfc, out, n);
}